// round 4
// baseline (speedup 1.0000x reference)
#include <cuda_runtime.h>
#include <cuda_bf16.h>

// Quaternion tensor product, HBM-bound (1.61 GB, ~7.1 TB/s achieved, 89% spec).
// R3 showed occupancy (58.6%) is surplus -> trade warps for per-warp MLP depth.
// R4: each thread processes the SAME float4 channel-group for TWO adjacent
// batches: 16 front-batched independent LDG.128 (MLP_p1=16), all warp accesses
// 512B contiguous. Streaming hints throughout (zero reuse).

__global__ __launch_bounds__(256) void quat_tp_kernel(
    const float4* __restrict__ in0,
    const float4* __restrict__ in1,
    float4* __restrict__ out)
{
    unsigned int idx = blockIdx.x * 256u + threadIdx.x;
    // batch-pair = idx >> 5 (covers batches 2p, 2p+1), group = idx & 31
    // base (float4 units) = pair*256 + group ; second batch at base + 128
    unsigned int base = ((idx >> 5) << 8) | (idx & 31u);

    // ---- 16 independent streaming loads, front-batched ----
    float4 a0 = __ldcs(in0 + base);
    float4 a1 = __ldcs(in0 + base + 32);
    float4 a2 = __ldcs(in0 + base + 64);
    float4 a3 = __ldcs(in0 + base + 96);
    float4 b0 = __ldcs(in1 + base);
    float4 b1 = __ldcs(in1 + base + 32);
    float4 b2 = __ldcs(in1 + base + 64);
    float4 b3 = __ldcs(in1 + base + 96);
    float4 c0 = __ldcs(in0 + base + 128);
    float4 c1 = __ldcs(in0 + base + 160);
    float4 c2 = __ldcs(in0 + base + 192);
    float4 c3 = __ldcs(in0 + base + 224);
    float4 d0 = __ldcs(in1 + base + 128);
    float4 d1 = __ldcs(in1 + base + 160);
    float4 d2 = __ldcs(in1 + base + 192);
    float4 d3 = __ldcs(in1 + base + 224);

    float4 o;

    // ---- batch 2p: Hamilton product (a, b) ----
    o.x = a0.x*b0.x - a1.x*b1.x - a2.x*b2.x - a3.x*b3.x;
    o.y = a0.y*b0.y - a1.y*b1.y - a2.y*b2.y - a3.y*b3.y;
    o.z = a0.z*b0.z - a1.z*b1.z - a2.z*b2.z - a3.z*b3.z;
    o.w = a0.w*b0.w - a1.w*b1.w - a2.w*b2.w - a3.w*b3.w;
    __stcs(out + base, o);

    o.x = a0.x*b1.x + a1.x*b0.x + a2.x*b3.x - a3.x*b2.x;
    o.y = a0.y*b1.y + a1.y*b0.y + a2.y*b3.y - a3.y*b2.y;
    o.z = a0.z*b1.z + a1.z*b0.z + a2.z*b3.z - a3.z*b2.z;
    o.w = a0.w*b1.w + a1.w*b0.w + a2.w*b3.w - a3.w*b2.w;
    __stcs(out + base + 32, o);

    o.x = a0.x*b2.x - a1.x*b3.x + a2.x*b0.x + a3.x*b1.x;
    o.y = a0.y*b2.y - a1.y*b3.y + a2.y*b0.y + a3.y*b1.y;
    o.z = a0.z*b2.z - a1.z*b3.z + a2.z*b0.z + a3.z*b1.z;
    o.w = a0.w*b2.w - a1.w*b3.w + a2.w*b0.w + a3.w*b1.w;
    __stcs(out + base + 64, o);

    o.x = a0.x*b3.x + a1.x*b2.x - a2.x*b1.x + a3.x*b0.x;
    o.y = a0.y*b3.y + a1.y*b2.y - a2.y*b1.y + a3.y*b0.y;
    o.z = a0.z*b3.z + a1.z*b2.z - a2.z*b1.z + a3.z*b0.z;
    o.w = a0.w*b3.w + a1.w*b2.w - a2.w*b1.w + a3.w*b0.w;
    __stcs(out + base + 96, o);

    // ---- batch 2p+1: Hamilton product (c, d) ----
    o.x = c0.x*d0.x - c1.x*d1.x - c2.x*d2.x - c3.x*d3.x;
    o.y = c0.y*d0.y - c1.y*d1.y - c2.y*d2.y - c3.y*d3.y;
    o.z = c0.z*d0.z - c1.z*d1.z - c2.z*d2.z - c3.z*d3.z;
    o.w = c0.w*d0.w - c1.w*d1.w - c2.w*d2.w - c3.w*d3.w;
    __stcs(out + base + 128, o);

    o.x = c0.x*d1.x + c1.x*d0.x + c2.x*d3.x - c3.x*d2.x;
    o.y = c0.y*d1.y + c1.y*d0.y + c2.y*d3.y - c3.y*d2.y;
    o.z = c0.z*d1.z + c1.z*d0.z + c2.z*d3.z - c3.z*d2.z;
    o.w = c0.w*d1.w + c1.w*d0.w + c2.w*d3.w - c3.w*d2.w;
    __stcs(out + base + 160, o);

    o.x = c0.x*d2.x - c1.x*d3.x + c2.x*d0.x + c3.x*d1.x;
    o.y = c0.y*d2.y - c1.y*d3.y + c2.y*d0.y + c3.y*d1.y;
    o.z = c0.z*d2.z - c1.z*d3.z + c2.z*d0.z + c3.z*d1.z;
    o.w = c0.w*d2.w - c1.w*d3.w + c2.w*d0.w + c3.w*d1.w;
    __stcs(out + base + 192, o);

    o.x = c0.x*d3.x + c1.x*d2.x - c2.x*d1.x + c3.x*d0.x;
    o.y = c0.y*d3.y + c1.y*d2.y - c2.y*d1.y + c3.y*d0.y;
    o.z = c0.z*d3.z + c1.z*d2.z - c2.z*d1.z + c3.z*d0.z;
    o.w = c0.w*d3.w + c1.w*d2.w - c2.w*d1.w + c3.w*d0.w;
    __stcs(out + base + 224, o);
}

extern "C" void kernel_launch(void* const* d_in, const int* in_sizes, int n_in,
                              void* d_out, int out_size) {
    const float4* in0 = (const float4*)d_in[0];
    const float4* in1 = (const float4*)d_in[1];
    float4* out = (float4*)d_out;

    // threads = (B/2) * 32 = out_size / 32  (out_size = B*512 floats)
    unsigned int threads_total = (unsigned int)((unsigned long long)out_size / 32ull);
    unsigned int grid = (threads_total + 255u) / 256u;
    quat_tp_kernel<<<grid, 256>>>(in0, in1, out);
}

// round 5
// speedup vs baseline: 1.0060x; 1.0060x over previous
#include <cuda_runtime.h>
#include <cuda_bf16.h>

// Quaternion tensor product, HBM-bound. R2-R4 established occupancy and MLP
// depth are both surplus; pinned at ~89% of HBM spec (~7.1 TB/s).
// R5 probe: sm_100+ 256-bit global accesses (ld/st.global.cs.v8.f32).
// Each warp instruction moves 1024B contiguous -> fewer LSU wavefronts/byte,
// denser line bursts. Layout: thread = one 8-float channel group, one batch.

struct F8 { float v[8]; };

__device__ __forceinline__ F8 ld256cs(const float* p) {
    F8 r;
    asm volatile("ld.global.cs.v8.f32 {%0,%1,%2,%3,%4,%5,%6,%7}, [%8];"
                 : "=f"(r.v[0]), "=f"(r.v[1]), "=f"(r.v[2]), "=f"(r.v[3]),
                   "=f"(r.v[4]), "=f"(r.v[5]), "=f"(r.v[6]), "=f"(r.v[7])
                 : "l"(p));
    return r;
}

__device__ __forceinline__ void st256cs(float* p, const F8& r) {
    asm volatile("st.global.cs.v8.f32 [%0], {%1,%2,%3,%4,%5,%6,%7,%8};"
                 :: "l"(p),
                    "f"(r.v[0]), "f"(r.v[1]), "f"(r.v[2]), "f"(r.v[3]),
                    "f"(r.v[4]), "f"(r.v[5]), "f"(r.v[6]), "f"(r.v[7])
                 : "memory");
}

__global__ __launch_bounds__(256) void quat_tp_kernel(
    const float* __restrict__ in0,
    const float* __restrict__ in1,
    float* __restrict__ out)
{
    unsigned int idx = blockIdx.x * 256u + threadIdx.x;
    // batch = idx >> 4, group g = idx & 15 (16 float8-groups per 128-ch segment)
    // base float offset = batch*512 + g*8 ; segment stride = 128 floats
    unsigned int base = ((idx >> 4) << 9) | ((idx & 15u) << 3);

    // 8 independent 256-bit streaming loads, front-batched.
    F8 a0 = ld256cs(in0 + base);
    F8 a1 = ld256cs(in0 + base + 128);
    F8 a2 = ld256cs(in0 + base + 256);
    F8 a3 = ld256cs(in0 + base + 384);
    F8 b0 = ld256cs(in1 + base);
    F8 b1 = ld256cs(in1 + base + 128);
    F8 b2 = ld256cs(in1 + base + 256);
    F8 b3 = ld256cs(in1 + base + 384);

    F8 o;

    // o0 = a0*b0 - a1*b1 - a2*b2 - a3*b3
    #pragma unroll
    for (int i = 0; i < 8; i++)
        o.v[i] = a0.v[i]*b0.v[i] - a1.v[i]*b1.v[i] - a2.v[i]*b2.v[i] - a3.v[i]*b3.v[i];
    st256cs(out + base, o);

    // o1 = a0*b1 + a1*b0 + a2*b3 - a3*b2
    #pragma unroll
    for (int i = 0; i < 8; i++)
        o.v[i] = a0.v[i]*b1.v[i] + a1.v[i]*b0.v[i] + a2.v[i]*b3.v[i] - a3.v[i]*b2.v[i];
    st256cs(out + base + 128, o);

    // o2 = a0*b2 - a1*b3 + a2*b0 + a3*b1
    #pragma unroll
    for (int i = 0; i < 8; i++)
        o.v[i] = a0.v[i]*b2.v[i] - a1.v[i]*b3.v[i] + a2.v[i]*b0.v[i] + a3.v[i]*b1.v[i];
    st256cs(out + base + 256, o);

    // o3 = a0*b3 + a1*b2 - a2*b1 + a3*b0
    #pragma unroll
    for (int i = 0; i < 8; i++)
        o.v[i] = a0.v[i]*b3.v[i] + a1.v[i]*b2.v[i] - a2.v[i]*b1.v[i] + a3.v[i]*b0.v[i];
    st256cs(out + base + 384, o);
}

extern "C" void kernel_launch(void* const* d_in, const int* in_sizes, int n_in,
                              void* d_out, int out_size) {
    const float* in0 = (const float*)d_in[0];
    const float* in1 = (const float*)d_in[1];
    float* out = (float*)d_out;

    // threads = B * 16 = out_size / 32
    unsigned int threads_total = (unsigned int)((unsigned long long)out_size / 32ull);
    unsigned int grid = (threads_total + 255u) / 256u;
    quat_tp_kernel<<<grid, 256>>>(in0, in1, out);
}